// round 2
// baseline (speedup 1.0000x reference)
#include <cuda_runtime.h>

// ---------------------------------------------------------------------------
// Problem constants
// ---------------------------------------------------------------------------
namespace {
constexpr int NPOST = 100000, NUSER = 50000, NENT = 20000;
constexpr int HID = 64;

constexpr long long OFF_HA_POST = 0;
constexpr long long OFF_HA_USER = OFF_HA_POST + (long long)NPOST * HID;
constexpr long long OFF_HA_ENT  = OFF_HA_USER + (long long)NUSER * HID;
constexpr long long OFF_HB_POST = OFF_HA_ENT  + (long long)NENT  * HID;
constexpr long long OFF_HB_USER = OFF_HB_POST + (long long)NPOST * HID;
constexpr long long OFF_HB_ENT  = OFF_HB_USER + (long long)NUSER * HID;
constexpr long long OFF_HS      = OFF_HB_ENT  + (long long)NENT  * HID;   // [NPOST, 128] max
constexpr long long OFF_ALS     = OFF_HS  + (long long)NPOST * 128;
constexpr long long OFF_ALD     = OFF_ALS + (long long)NPOST * 2;
constexpr long long OFF_M       = OFF_ALD + (long long)NPOST * 2;
constexpr long long OFF_S       = OFF_M   + (long long)NPOST * 2;
constexpr long long OFF_P       = OFF_S   + (long long)NPOST * 2;
constexpr long long TOTAL_SCRATCH = OFF_P + 800000;  // max E * 2
}  // namespace

__device__ __align__(256) float g_scratch[TOTAL_SCRATCH];

// ---------------------------------------------------------------------------
// Ordered-int float max helpers (monotonic bijection float <-> int)
// ---------------------------------------------------------------------------
__device__ __forceinline__ int f2o(float f) {
    int i = __float_as_int(f);
    return i >= 0 ? i : (i ^ 0x7FFFFFFF);
}
__device__ __forceinline__ float o2f(int k) {
    return __int_as_float(k >= 0 ? k : (k ^ 0x7FFFFFFF));
}
#define NEG_INF_KEY ((int)0x807FFFFF)  // f2o(-inf)

// ---------------------------------------------------------------------------
// Generic fp32 GEMM:  C[M, BN] = A[M, K] @ B[BN, K]^T  (+bias, +relu)
// BM=128 rows/block, 8x4 register tiles, BK=16. threads = 16*(BN/4).
// ---------------------------------------------------------------------------
template <int BN, bool BIAS, bool RELU>
__global__ void gemm_nt(const float* __restrict__ A, const float* __restrict__ B,
                        const float* __restrict__ bias, float* __restrict__ C,
                        int M, int K) {
    constexpr int BM = 128, BK = 16, TM = 8, TN = 4;
    constexpr int THREADS = (BM / TM) * (BN / TN);
    __shared__ float As[BK][BM + 4];
    __shared__ float Bs[BK][BN + 4];

    const int t  = threadIdx.x;
    const int m0 = blockIdx.x * BM;
    const int jc = (t % (BN / TN)) * TN;
    const int ir = (t / (BN / TN)) * TM;

    float acc[TM][TN];
#pragma unroll
    for (int i = 0; i < TM; i++)
#pragma unroll
        for (int j = 0; j < TN; j++) acc[i][j] = 0.f;

    for (int k0 = 0; k0 < K; k0 += BK) {
        constexpr int A4 = BM * BK / 4;
#pragma unroll
        for (int q = t; q < A4; q += THREADS) {
            int row = q / (BK / 4);
            int kq  = (q % (BK / 4)) * 4;
            int gr  = m0 + row;
            if (gr >= M) gr = M - 1;  // clamp; stores are guarded
            float4 v = *reinterpret_cast<const float4*>(&A[(size_t)gr * K + k0 + kq]);
            As[kq][row] = v.x; As[kq + 1][row] = v.y;
            As[kq + 2][row] = v.z; As[kq + 3][row] = v.w;
        }
        constexpr int B4 = BN * BK / 4;
#pragma unroll
        for (int q = t; q < B4; q += THREADS) {
            int row = q / (BK / 4);
            int kq  = (q % (BK / 4)) * 4;
            float4 v = *reinterpret_cast<const float4*>(&B[(size_t)row * K + k0 + kq]);
            Bs[kq][row] = v.x; Bs[kq + 1][row] = v.y;
            Bs[kq + 2][row] = v.z; Bs[kq + 3][row] = v.w;
        }
        __syncthreads();
#pragma unroll
        for (int kk = 0; kk < BK; kk++) {
            float ra[TM], rb[TN];
            float4 b4 = *reinterpret_cast<const float4*>(&Bs[kk][jc]);
            rb[0] = b4.x; rb[1] = b4.y; rb[2] = b4.z; rb[3] = b4.w;
            float4 a0 = *reinterpret_cast<const float4*>(&As[kk][ir]);
            float4 a1 = *reinterpret_cast<const float4*>(&As[kk][ir + 4]);
            ra[0] = a0.x; ra[1] = a0.y; ra[2] = a0.z; ra[3] = a0.w;
            ra[4] = a1.x; ra[5] = a1.y; ra[6] = a1.z; ra[7] = a1.w;
#pragma unroll
            for (int i = 0; i < TM; i++)
#pragma unroll
                for (int j = 0; j < TN; j++) acc[i][j] += ra[i] * rb[j];
        }
        __syncthreads();
    }

#pragma unroll
    for (int i = 0; i < TM; i++) {
        int gr = m0 + ir + i;
        if (gr < M) {
#pragma unroll
            for (int j = 0; j < TN; j++) {
                float v = acc[i][j];
                if (BIAS) v += bias[jc + j];
                if (RELU) v = fmaxf(v, 0.f);
                C[(size_t)gr * BN + jc + j] = v;
            }
        }
    }
}

// ---------------------------------------------------------------------------
// Attention logits: al[n,h] = x[n,:] @ v[h,:],  v[h,k] = sum_c W[h*64+c,k]*a[h,c]
// ---------------------------------------------------------------------------
__global__ void logits_kernel(const float* __restrict__ x, int N,
                              const float* __restrict__ W, const float* __restrict__ a,
                              float* __restrict__ al) {
    __shared__ float v[2][64];
    const int t = threadIdx.x;
    if (t < 128) {
        int h = t >> 6, k = t & 63;
        float sum = 0.f;
#pragma unroll
        for (int c = 0; c < 64; c++) sum += W[(h * 64 + c) * 64 + k] * a[h * 64 + c];
        v[h][k] = sum;
    }
    __syncthreads();
    int g = blockIdx.x * blockDim.x + t;
    if (g < N * 2) {
        int n = g >> 1, h = g & 1;
        const float4* xr = reinterpret_cast<const float4*>(x + (size_t)n * 64);
        float s = 0.f;
#pragma unroll
        for (int k4 = 0; k4 < 16; k4++) {
            float4 xv = xr[k4];
            s += xv.x * v[h][k4 * 4] + xv.y * v[h][k4 * 4 + 1] +
                 xv.z * v[h][k4 * 4 + 2] + xv.w * v[h][k4 * 4 + 3];
        }
        al[g] = s;
    }
}

// ---------------------------------------------------------------------------
// Small helpers
// ---------------------------------------------------------------------------
__global__ void zero_kernel(float* __restrict__ p, long long n) {
    long long i = ((long long)blockIdx.x * blockDim.x + threadIdx.x) * 4;
    if (i < n) *reinterpret_cast<float4*>(p + i) = make_float4(0.f, 0.f, 0.f, 0.f);
}

__global__ void init_ms_kernel(int* __restrict__ m, float* __restrict__ s, int n2) {
    int i = blockIdx.x * blockDim.x + threadIdx.x;
    if (i < n2) { m[i] = NEG_INF_KEY; s[i] = 0.f; }
}

__global__ void rcp_kernel(float* __restrict__ s, int n2) {
    int i = blockIdx.x * blockDim.x + threadIdx.x;
    if (i < n2) s[i] = 1.0f / (s[i] + 1e-16f);
}

// ---------------------------------------------------------------------------
// Edge pass 1: segment max (ordered-int atomicMax)
// ---------------------------------------------------------------------------
__global__ void edge_max_kernel(const int* __restrict__ src, const int* __restrict__ dst,
                                int E, const float* __restrict__ als,
                                const float* __restrict__ ald, int* __restrict__ m) {
    int e = blockIdx.x * blockDim.x + threadIdx.x;
    if (e >= E) return;
    int s = src[e], d = dst[e];
#pragma unroll
    for (int h = 0; h < 2; h++) {
        float v = als[s * 2 + h] + ald[d * 2 + h];
        v = v < 0.f ? 0.2f * v : v;
        atomicMax(&m[d * 2 + h], f2o(v));
    }
}

// ---------------------------------------------------------------------------
// Edge pass 2: p = exp(e - m), store p, accumulate s
// ---------------------------------------------------------------------------
__global__ void edge_p_kernel(const int* __restrict__ src, const int* __restrict__ dst,
                              int E, const float* __restrict__ als,
                              const float* __restrict__ ald, const int* __restrict__ m,
                              float* __restrict__ p, float* __restrict__ ssum) {
    int e = blockIdx.x * blockDim.x + threadIdx.x;
    if (e >= E) return;
    int s = src[e], d = dst[e];
#pragma unroll
    for (int h = 0; h < 2; h++) {
        float v = als[s * 2 + h] + ald[d * 2 + h];
        v = v < 0.f ? 0.2f * v : v;
        float pe = __expf(v - o2f(m[d * 2 + h]));
        p[(size_t)e * 2 + h] = pe;
        atomicAdd(&ssum[d * 2 + h], pe);
    }
}

// ---------------------------------------------------------------------------
// Edge pass 3: acc[dst, c] += 0.5*(a0*hs[src,0,c] + a1*hs[src,1,c])
// 16 lanes per edge; red.global.add.v4.f32 scatter.
// rs holds 1/(s+eps).
// ---------------------------------------------------------------------------
__global__ void edge_acc_kernel(const int* __restrict__ src, const int* __restrict__ dst,
                                int E, const float* __restrict__ p,
                                const float* __restrict__ rs,
                                const float* __restrict__ hs, float* __restrict__ acc) {
    int t = blockIdx.x * blockDim.x + threadIdx.x;
    int e = t >> 4;
    if (e >= E) return;
    int lane = t & 15;
    int sn = src[e], d = dst[e];
    float a0 = 0.5f * p[(size_t)e * 2]     * rs[d * 2];
    float a1 = 0.5f * p[(size_t)e * 2 + 1] * rs[d * 2 + 1];
    const float* hrow = hs + (size_t)sn * 128;
    float4 h0 = *reinterpret_cast<const float4*>(hrow + lane * 4);
    float4 h1 = *reinterpret_cast<const float4*>(hrow + 64 + lane * 4);
    float4 r;
    r.x = a0 * h0.x + a1 * h1.x;
    r.y = a0 * h0.y + a1 * h1.y;
    r.z = a0 * h0.z + a1 * h1.z;
    r.w = a0 * h0.w + a1 * h1.w;
    float* dp = acc + (size_t)d * 64 + lane * 4;
    asm volatile("red.global.add.v4.f32 [%0], {%1,%2,%3,%4};"
                 :: "l"(dp), "f"(r.x), "f"(r.y), "f"(r.z), "f"(r.w) : "memory");
}

// ---------------------------------------------------------------------------
// Finalize: h = relu(acc + sum of per-relation biases)
// ---------------------------------------------------------------------------
__global__ void finalize_kernel(float* __restrict__ h, const float* __restrict__ gatb,
                                int b0, int b1, int b2, int nrel, long long n) {
    long long i = (long long)blockIdx.x * blockDim.x + threadIdx.x;
    if (i >= n) return;
    int c = (int)(i & 63);
    float b = gatb[b0 + c];
    if (nrel > 1) b += gatb[b1 + c];
    if (nrel > 2) b += gatb[b2 + c];
    h[i] = fmaxf(h[i] + b, 0.f);
}

// ---------------------------------------------------------------------------
// Classifier: out[n] = relu(h[n] @ w1^T + b1) @ w2^T + b2  (one warp / node)
// ---------------------------------------------------------------------------
__global__ void cls_kernel(const float* __restrict__ h, const float* __restrict__ w1,
                           const float* __restrict__ b1, const float* __restrict__ w2,
                           const float* __restrict__ b2, float* __restrict__ out, int N) {
    __shared__ float sw1t[64 * 33];  // transposed, padded: sw1t[k*33 + j]
    __shared__ float sw2[32], sb1[32];
    for (int i = threadIdx.x; i < 2048; i += blockDim.x) {
        int j = i / 64, k = i % 64;
        sw1t[k * 33 + j] = w1[i];
    }
    if (threadIdx.x < 32) { sw2[threadIdx.x] = w2[threadIdx.x]; sb1[threadIdx.x] = b1[threadIdx.x]; }
    __syncthreads();
    int warp = threadIdx.x >> 5, lane = threadIdx.x & 31;
    int n = blockIdx.x * 8 + warp;
    if (n >= N) return;
    const float4* hr = reinterpret_cast<const float4*>(h + (size_t)n * 64);
    float t = 0.f;
#pragma unroll
    for (int k4 = 0; k4 < 16; k4++) {
        float4 hv = hr[k4];
        int k = k4 * 4;
        t += hv.x * sw1t[(k    ) * 33 + lane] + hv.y * sw1t[(k + 1) * 33 + lane] +
             hv.z * sw1t[(k + 2) * 33 + lane] + hv.w * sw1t[(k + 3) * 33 + lane];
    }
    t = fmaxf(t + sb1[lane], 0.f);
    float o = t * sw2[lane];
#pragma unroll
    for (int off = 16; off; off >>= 1) o += __shfl_down_sync(0xffffffffu, o, off);
    if (lane == 0) out[n] = o + b2[0];
}

// ---------------------------------------------------------------------------
// Host orchestration (graph-capturable: kernel launches only)
// ---------------------------------------------------------------------------
extern "C" void kernel_launch(void* const* d_in, const int* in_sizes, int n_in,
                              void* d_out, int out_size) {
    float* S = nullptr;
    cudaGetSymbolAddress((void**)&S, g_scratch);

    const float* x_post = (const float*)d_in[0];
    const float* x_user = (const float*)d_in[1];
    const float* x_ent  = (const float*)d_in[2];
    const int* esrc[6] = {(const int*)d_in[3], (const int*)d_in[5], (const int*)d_in[7],
                          (const int*)d_in[9], (const int*)d_in[11], (const int*)d_in[13]};
    const int* edst[6] = {(const int*)d_in[4], (const int*)d_in[6], (const int*)d_in[8],
                          (const int*)d_in[10], (const int*)d_in[12], (const int*)d_in[14]};
    const int Ecnt[6] = {100000, 200000, 200000, 400000, 400000, 250000};
    const int srcT[6] = {1, 1, 0, 1, 1, 0};
    const int dstT[6] = {0, 0, 2, 1, 1, 0};
    const int Ntype[3] = {NPOST, NUSER, NENT};

    const float* pw = (const float*)d_in[15]; const float* pb = (const float*)d_in[16];
    const float* uw = (const float*)d_in[17]; const float* ub = (const float*)d_in[18];
    const float* ew = (const float*)d_in[19]; const float* eb = (const float*)d_in[20];
    const float* Wsrc = (const float*)d_in[21];
    const float* Wdst = (const float*)d_in[22];
    const float* asrc = (const float*)d_in[23];
    const float* adst = (const float*)d_in[24];
    const float* gatb = (const float*)d_in[25];
    const float* w1 = (const float*)d_in[26]; const float* b1 = (const float*)d_in[27];
    const float* w2 = (const float*)d_in[28]; const float* b2 = (const float*)d_in[29];
    float* out = (float*)d_out;

    float* hA[3] = {S + OFF_HA_POST, S + OFF_HA_USER, S + OFF_HA_ENT};
    float* hB[3] = {S + OFF_HB_POST, S + OFF_HB_USER, S + OFF_HB_ENT};
    float* hs   = S + OFF_HS;
    float* als  = S + OFF_ALS;
    float* ald  = S + OFF_ALD;
    int*   mkey = (int*)(S + OFF_M);
    float* ssum = S + OFF_S;
    float* pbuf = S + OFF_P;

    // Input projections
    gemm_nt<64, true, false><<<(NPOST + 127) / 128, 256>>>(x_post, pw, pb, hA[0], NPOST, 768);
    gemm_nt<64, true, false><<<(NUSER + 127) / 128, 256>>>(x_user, uw, ub, hA[1], NUSER, 32);
    gemm_nt<64, true, false><<<(NENT  + 127) / 128, 256>>>(x_ent,  ew, eb, hA[2], NENT, 64);

    const long long hcnt = (long long)(NPOST + NUSER + NENT) * HID;

    for (int l = 0; l < 2; l++) {
        float** cur = (l == 0) ? hA : hB;
        float** nxt = (l == 0) ? hB : hA;
        zero_kernel<<<(int)((hcnt / 4 + 255) / 256), 256>>>(nxt[0], hcnt);

        for (int r = 0; r < 6; r++) {
            int Ns = Ntype[srcT[r]], Nd = Ntype[dstT[r]], E = Ecnt[r];
            const float* Ws  = Wsrc + (long long)(l * 6 + r) * 8192;
            const float* Wd  = Wdst + (long long)(l * 6 + r) * 8192;
            const float* as_ = asrc + (long long)(l * 6 + r) * 128;
            const float* ad_ = adst + (long long)(l * 6 + r) * 128;

            gemm_nt<128, false, false><<<(Ns + 127) / 128, 512>>>(cur[srcT[r]], Ws, nullptr, hs, Ns, 64);
            logits_kernel<<<(Ns * 2 + 255) / 256, 256>>>(cur[srcT[r]], Ns, Ws, as_, als);
            logits_kernel<<<(Nd * 2 + 255) / 256, 256>>>(cur[dstT[r]], Nd, Wd, ad_, ald);
            init_ms_kernel<<<(Nd * 2 + 255) / 256, 256>>>(mkey, ssum, Nd * 2);
            edge_max_kernel<<<(E + 255) / 256, 256>>>(esrc[r], edst[r], E, als, ald, mkey);
            edge_p_kernel<<<(E + 255) / 256, 256>>>(esrc[r], edst[r], E, als, ald, mkey, pbuf, ssum);
            rcp_kernel<<<(Nd * 2 + 255) / 256, 256>>>(ssum, Nd * 2);
            edge_acc_kernel<<<(E * 16 + 255) / 256, 256>>>(esrc[r], edst[r], E, pbuf, ssum, hs, nxt[dstT[r]]);
        }

        finalize_kernel<<<(int)(((long long)NPOST * 64 + 255) / 256), 256>>>(
            nxt[0], gatb, (l * 6 + 0) * 64, (l * 6 + 1) * 64, (l * 6 + 5) * 64, 3, (long long)NPOST * 64);
        finalize_kernel<<<(int)(((long long)NUSER * 64 + 255) / 256), 256>>>(
            nxt[1], gatb, (l * 6 + 3) * 64, (l * 6 + 4) * 64, 0, 2, (long long)NUSER * 64);
        finalize_kernel<<<(int)(((long long)NENT * 64 + 255) / 256), 256>>>(
            nxt[2], gatb, (l * 6 + 2) * 64, 0, 0, 1, (long long)NENT * 64);
    }

    cls_kernel<<<(NPOST + 7) / 8, 256>>>(hA[0], w1, b1, w2, b2, out, NPOST);
}